// round 16
// baseline (speedup 1.0000x reference)
#include <cuda_runtime.h>
#include <cuda_bf16.h>
#include <math.h>
#include <stdint.h>

#define B_ 16
#define S_ 2048
#define D_ 1024
#define H_ 128
#define M_ (B_ * S_)   // 32768

// Split operands in global (bf16 hi/lo)
__device__ __nv_bfloat16 g_ah[(size_t)M_ * D_];   // input hi
__device__ __nv_bfloat16 g_al[(size_t)M_ * D_];   // input lo
__device__ __nv_bfloat16 g_wth[3 * H_ * D_];      // W transposed [mat][n][k] hi
__device__ __nv_bfloat16 g_wtl[3 * H_ * D_];      // lo
__device__ __nv_bfloat16 g_qh[(size_t)M_ * H_], g_ql[(size_t)M_ * H_];
__device__ __nv_bfloat16 g_kh[(size_t)M_ * H_], g_kl[(size_t)M_ * H_];
__device__ __nv_bfloat16 g_vh[(size_t)M_ * H_], g_vl[(size_t)M_ * H_];

// ===========================================================================
// Helpers
// ===========================================================================
__device__ __forceinline__ uint32_t smem_u32(const void* p) {
    uint32_t a;
    asm("{ .reg .u64 t; cvta.to.shared.u64 t, %1; cvt.u32.u64 %0, t; }"
        : "=r"(a) : "l"(p));
    return a;
}
__device__ __forceinline__ void ldsm4(uint32_t r[4], uint32_t addr) {
    asm volatile("ldmatrix.sync.aligned.m8n8.x4.shared.b16 {%0,%1,%2,%3}, [%4];"
                 : "=r"(r[0]), "=r"(r[1]), "=r"(r[2]), "=r"(r[3]) : "r"(addr));
}
__device__ __forceinline__ void ldsm4t(uint32_t r[4], uint32_t addr) {
    asm volatile("ldmatrix.sync.aligned.m8n8.x4.trans.shared.b16 {%0,%1,%2,%3}, [%4];"
                 : "=r"(r[0]), "=r"(r[1]), "=r"(r[2]), "=r"(r[3]) : "r"(addr));
}
__device__ __forceinline__ void mma16816(float c[4], const uint32_t a[4],
                                         uint32_t b0, uint32_t b1) {
    asm volatile(
        "mma.sync.aligned.m16n8k16.row.col.f32.bf16.bf16.f32 "
        "{%0,%1,%2,%3}, {%4,%5,%6,%7}, {%8,%9}, {%0,%1,%2,%3};"
        : "+f"(c[0]), "+f"(c[1]), "+f"(c[2]), "+f"(c[3])
        : "r"(a[0]), "r"(a[1]), "r"(a[2]), "r"(a[3]), "r"(b0), "r"(b1));
}
__device__ __forceinline__ void split2(float x0, float x1,
                                       uint32_t& hi, uint32_t& lo) {
    __nv_bfloat16 h0 = __float2bfloat16_rn(x0);
    __nv_bfloat16 h1 = __float2bfloat16_rn(x1);
    __nv_bfloat162 hp; hp.x = h0; hp.y = h1;
    hi = *reinterpret_cast<uint32_t*>(&hp);
    __nv_bfloat162 lp = __floats2bfloat162_rn(x0 - __bfloat162float(h0),
                                              x1 - __bfloat162float(h1));
    lo = *reinterpret_cast<uint32_t*>(&lp);
}
__device__ __forceinline__ void cpa(uint32_t dst, const void* src) {
    asm volatile("cp.async.cg.shared.global [%0], [%1], 16;"
                 :: "r"(dst), "l"(src) : "memory");
}
#define CP_COMMIT() asm volatile("cp.async.commit_group;" ::: "memory")
#define CP_WAIT(n)  asm volatile("cp.async.wait_group %0;" :: "n"(n) : "memory")
#define BARP(id)    asm volatile("bar.sync %0, 64;" :: "r"(id) : "memory")

// ===========================================================================
// Convert kernels: fp32 -> split bf16 (once, outside the hot loops)
// ===========================================================================
__global__ __launch_bounds__(256)
void conv_a(const float* __restrict__ A)
{
    size_t i = ((size_t)blockIdx.x * 256 + threadIdx.x) * 4;
    float4 v = *(const float4*)(A + i);
    uint32_t h0, l0, h1, l1;
    split2(v.x, v.y, h0, l0);
    split2(v.z, v.w, h1, l1);
    *(uint2*)&g_ah[i] = make_uint2(h0, h1);
    *(uint2*)&g_al[i] = make_uint2(l0, l1);
}

__global__ __launch_bounds__(256)
void conv_w(const float* __restrict__ Wq, const float* __restrict__ Wk,
            const float* __restrict__ Wv)
{
    const int mat = blockIdx.y;
    const float* W = (mat == 0) ? Wq : (mat == 1) ? Wk : Wv;
    int idx = blockIdx.x * 256 + threadIdx.x;   // 0..131071
    int k = idx >> 7, n = idx & 127;
    float x = W[(size_t)k * H_ + n];
    __nv_bfloat16 h = __float2bfloat16_rn(x);
    size_t o = (size_t)mat * (H_ * D_) + (size_t)n * D_ + k;
    g_wth[o] = h;
    g_wtl[o] = __float2bfloat16_rn(x - __bfloat162float(h));
}

// ===========================================================================
// QKV GEMM: C[M,H] = A[M,D] @ W[D,H], blockIdx.y selects matrix.
// 128x128 tile, BK=64, 8 warps (4Mx2N, warp tile 32x64), SINGLE stage,
// 2 CTAs/SM (the co-resident CTA hides the load phase).
// Stage layout: Ah 0 | Al 18432 | Bh 36864 | Bl 55296
// ===========================================================================
#define GST    144       // smem row stride bytes (64 bf16 + pad)
#define G_SMEM 73728

__global__ __launch_bounds__(256, 2)
void qkv_mma(void)
{
    extern __shared__ char sm[];
    const uint32_t sb = smem_u32(sm);
    const int tid  = threadIdx.x;
    const int lane = tid & 31;
    const int wid  = tid >> 5;
    const int wm   = wid & 3;      // 32-row slice
    const int wn   = wid >> 2;     // 64-col slice
    const int m0   = blockIdx.x * 128;
    const int mat  = blockIdx.y;

    const int a_r = lane & 15;
    const int a_k = (lane >> 4) * 16;
    const int b_n = (lane & 7) + ((lane >> 4) << 3);
    const int b_k = ((lane >> 3) & 1) * 16;

    const __nv_bfloat16* wth = g_wth + (size_t)mat * (H_ * D_);
    const __nv_bfloat16* wtl = g_wtl + (size_t)mat * (H_ * D_);

    float acc[2][8][4];
#pragma unroll
    for (int i = 0; i < 2; i++)
#pragma unroll
        for (int j = 0; j < 8; j++)
#pragma unroll
            for (int e = 0; e < 4; e++) acc[i][j][e] = 0.f;

    for (int c = 0; c < 16; c++) {
        const int c0 = c * 64;
        __syncthreads();   // previous chunk consumed by all warps
#pragma unroll
        for (int j = 0; j < 16; j++) {
            int it   = tid + j * 256;
            int tile = it >> 10;          // 0:Ah 1:Al 2:Bh 3:Bl
            int r    = (it >> 3) & 127;
            int seg  = it & 7;
            const __nv_bfloat16* src;
            if (tile == 0)      src = g_ah + (size_t)(m0 + r) * D_ + c0 + seg * 8;
            else if (tile == 1) src = g_al + (size_t)(m0 + r) * D_ + c0 + seg * 8;
            else if (tile == 2) src = wth + (size_t)r * D_ + c0 + seg * 8;
            else                src = wtl + (size_t)r * D_ + c0 + seg * 8;
            cpa(sb + tile * 18432 + r * GST + seg * 16, src);
        }
        CP_COMMIT();
        CP_WAIT(0);
        __syncthreads();

#pragma unroll
        for (int ks = 0; ks < 4; ks++) {
            const int kb = ks * 32;
            uint32_t ah[2][4], al[2][4];
#pragma unroll
            for (int mt = 0; mt < 2; mt++) {
                uint32_t base = sb + (uint32_t)((wm * 32 + mt * 16 + a_r) * GST + kb + a_k);
                ldsm4(ah[mt], base);
                ldsm4(al[mt], base + 18432);
            }
            uint32_t bh[8][2], bl[8][2];
#pragma unroll
            for (int ntp = 0; ntp < 4; ntp++) {
                uint32_t base = sb + 36864 +
                    (uint32_t)((wn * 64 + ntp * 16 + b_n) * GST + kb + b_k);
                uint32_t r4[4];
                ldsm4(r4, base);
                bh[2 * ntp][0] = r4[0]; bh[2 * ntp][1] = r4[1];
                bh[2 * ntp + 1][0] = r4[2]; bh[2 * ntp + 1][1] = r4[3];
                ldsm4(r4, base + 18432);
                bl[2 * ntp][0] = r4[0]; bl[2 * ntp][1] = r4[1];
                bl[2 * ntp + 1][0] = r4[2]; bl[2 * ntp + 1][1] = r4[3];
            }
#pragma unroll
            for (int mt = 0; mt < 2; mt++)
#pragma unroll
                for (int nt = 0; nt < 8; nt++) {
                    mma16816(acc[mt][nt], ah[mt], bh[nt][0], bh[nt][1]);
                    mma16816(acc[mt][nt], ah[mt], bl[nt][0], bl[nt][1]);
                    mma16816(acc[mt][nt], al[mt], bh[nt][0], bh[nt][1]);
                }
        }
    }

    // Epilogue: write split bf16; fold softmax scale into Q
    const float qs = (mat == 0) ? 0.08838834764831845f : 1.f;
    __nv_bfloat16* Ch = (mat == 0) ? g_qh : (mat == 1) ? g_kh : g_vh;
    __nv_bfloat16* Cl = (mat == 0) ? g_ql : (mat == 1) ? g_kl : g_vl;
#pragma unroll
    for (int mt = 0; mt < 2; mt++)
#pragma unroll
        for (int nt = 0; nt < 8; nt++) {
            int r  = m0 + wm * 32 + mt * 16 + (lane >> 2);
            int cc = wn * 64 + nt * 8 + (lane & 3) * 2;
            uint32_t hi, lo;
            split2(acc[mt][nt][0] * qs, acc[mt][nt][1] * qs, hi, lo);
            *(uint32_t*)&Ch[(size_t)r * H_ + cc] = hi;
            *(uint32_t*)&Cl[(size_t)r * H_ + cc] = lo;
            split2(acc[mt][nt][2] * qs, acc[mt][nt][3] * qs, hi, lo);
            *(uint32_t*)&Ch[(size_t)(r + 8) * H_ + cc] = hi;
            *(uint32_t*)&Cl[(size_t)(r + 8) * H_ + cc] = lo;
        }
}

// ===========================================================================
// Causal flash attention, 512 threads (16 warps).
// Warp pair p owns q-rows [p*16,+16); the two warps split the 64-key block
// 32/32 (partial O merged in epilogue). Softmax max/sum combined across the
// pair via smem + pair-local named barriers (no CTA-wide coupling).
// smem: Q (Qh 0, Ql 34816) | K stage0 69632 | K stage1 104448 | V 139264 |
//       softmax exch 174080 (2KB).  Row stride 272.
// ===========================================================================
#define AST     272
#define AK_OFF  69632
#define AV_OFF  139264
#define ASF_OFF 174080
#define A_SMEM  176128

__global__ __launch_bounds__(512, 1)
void attn_mma(float* __restrict__ out)
{
    extern __shared__ char sm[];
    const uint32_t sb = smem_u32(sm);
    const int tid  = threadIdx.x;
    const int lane = tid & 31;
    const int wid  = tid >> 5;       // 0..15
    const int p    = wid >> 1;       // pair 0..7 -> rows [p*16,+16)
    const int w2   = wid & 1;        // key half: keys [w2*32,+32) of block
    const int qb   = (int)(gridDim.x - 1 - blockIdx.x);  // heavy-first
    const int b    = blockIdx.y;

    const int a_r = lane & 15;
    const int a_k = (lane >> 4) * 16;
    const int b_n = (lane & 7) + ((lane >> 4) << 3);
    const int b_k = ((lane >> 3) & 1) * 16;
    const int v_key = lane & 15;
    const int v_h   = (lane >> 4) * 16;

    const size_t qel = ((size_t)b * S_ + (size_t)qb * 128) * H_;

    // Stage Q (group 0)
#pragma unroll
    for (int j = 0; j < 8; j++) {
        int it   = tid + j * 512;
        int tile = it >> 11;              // 0:Qh 1:Ql
        int r    = (it >> 4) & 127;
        int seg  = it & 15;
        cpa(sb + tile * 34816 + r * AST + seg * 16,
            (tile ? g_ql : g_qh) + qel + (size_t)r * H_ + seg * 8);
    }
    CP_COMMIT();

    auto issue_k = [&](int kb, int s) {
        const size_t kel = ((size_t)b * S_ + (size_t)kb * 64) * H_;
        const uint32_t base = sb + AK_OFF + s * 34816;
#pragma unroll
        for (int j = 0; j < 4; j++) {
            int it   = tid + j * 512;
            int tile = it >> 10;          // 0:Kh 1:Kl
            int r    = (it >> 4) & 63;
            int seg  = it & 15;
            cpa(base + tile * 17408 + r * AST + seg * 16,
                (tile ? g_kl : g_kh) + kel + (size_t)r * H_ + seg * 8);
        }
    };
    auto issue_v = [&](int kb) {
        const size_t kel = ((size_t)b * S_ + (size_t)kb * 64) * H_;
        const uint32_t base = sb + AV_OFF;
#pragma unroll
        for (int j = 0; j < 4; j++) {
            int it   = tid + j * 512;
            int tile = it >> 10;          // 0:Vh 1:Vl
            int r    = (it >> 4) & 63;
            int seg  = it & 15;
            cpa(base + tile * 17408 + r * AST + seg * 16,
                (tile ? g_vl : g_vh) + kel + (size_t)r * H_ + seg * 8);
        }
    };

    issue_k(0, 0);
    CP_COMMIT();
    CP_WAIT(1);          // Q complete (K0 still in flight)
    __syncthreads();     // Q visible

    float O[16][4];
#pragma unroll
    for (int nt = 0; nt < 16; nt++)
#pragma unroll
        for (int e = 0; e < 4; e++) O[nt][e] = 0.f;
    float mA = -INFINITY, mB = -INFINITY, lA = 0.f, lB = 0.f;

    float* sfm = (float*)(sm + ASF_OFF);        // 256 floats: row max
    float* sfs = sfm + 256;                     // 256 floats: row sum
    const int rA = p * 16 + (lane >> 2);
    const int rB = rA + 8;
    const int barid = 1 + p;

    const uint32_t qa  = sb + (uint32_t)((p * 16 + a_r) * AST + a_k);
    const uint32_t kfx = (uint32_t)((w2 * 32 + b_n) * AST + b_k);
    const uint32_t vfx = (uint32_t)((w2 * 32 + v_key) * AST + v_h);

    const int kb_end = 2 * qb + 1;
    for (int kb = 0; kb <= kb_end; kb++) {
        const bool pre = (kb + 1 <= kb_end);
        CP_WAIT(0);        // K(kb) complete
        __syncthreads();   // K visible; V buffer free (all PV(kb-1) done)
        issue_v(kb);  CP_COMMIT();
        if (pre) { issue_k(kb + 1, (kb + 1) & 1); CP_COMMIT(); }

        // ---- S = Q K^T on this warp's 32 keys ----
        float s[4][4];
#pragma unroll
        for (int nt = 0; nt < 4; nt++)
#pragma unroll
            for (int e = 0; e < 4; e++) s[nt][e] = 0.f;

        const uint32_t kst = sb + AK_OFF + (kb & 1) * 34816 + kfx;
#pragma unroll
        for (int ks = 0; ks < 8; ks++) {
            uint32_t qh[4], ql[4];
            ldsm4(qh, qa + ks * 32);
            ldsm4(ql, qa + 34816 + ks * 32);
            uint32_t kh[4][2], kl[4][2];
#pragma unroll
            for (int g = 0; g < 2; g++) {
                uint32_t ka = kst + (uint32_t)(g * 16 * AST + ks * 32);
                uint32_t r4[4];
                ldsm4(r4, ka);
                kh[2 * g][0] = r4[0]; kh[2 * g][1] = r4[1];
                kh[2 * g + 1][0] = r4[2]; kh[2 * g + 1][1] = r4[3];
                ldsm4(r4, ka + 17408);
                kl[2 * g][0] = r4[0]; kl[2 * g][1] = r4[1];
                kl[2 * g + 1][0] = r4[2]; kl[2 * g + 1][1] = r4[3];
            }
#pragma unroll
            for (int nt = 0; nt < 4; nt++) {
                mma16816(s[nt], qh, kh[nt][0], kh[nt][1]);
                mma16816(s[nt], qh, kl[nt][0], kl[nt][1]);
                mma16816(s[nt], ql, kh[nt][0], kh[nt][1]);
            }
        }

        // ---- mask ----
        const int grA = qb * 128 + rA;
        if (kb >= 2 * qb) {
#pragma unroll
            for (int nt = 0; nt < 4; nt++) {
                int c0 = kb * 64 + w2 * 32 + nt * 8 + (lane & 3) * 2;
                if (c0 > grA)         s[nt][0] = -INFINITY;
                if (c0 + 1 > grA)     s[nt][1] = -INFINITY;
                if (c0 > grA + 8)     s[nt][2] = -INFINITY;
                if (c0 + 1 > grA + 8) s[nt][3] = -INFINITY;
            }
        }

        // ---- online softmax: local reduce + pair exchange ----
        float mxA = -INFINITY, mxB = -INFINITY;
#pragma unroll
        for (int nt = 0; nt < 4; nt++) {
            mxA = fmaxf(mxA, fmaxf(s[nt][0], s[nt][1]));
            mxB = fmaxf(mxB, fmaxf(s[nt][2], s[nt][3]));
        }
        mxA = fmaxf(mxA, __shfl_xor_sync(0xffffffffu, mxA, 1));
        mxA = fmaxf(mxA, __shfl_xor_sync(0xffffffffu, mxA, 2));
        mxB = fmaxf(mxB, __shfl_xor_sync(0xffffffffu, mxB, 1));
        mxB = fmaxf(mxB, __shfl_xor_sync(0xffffffffu, mxB, 2));
        if ((lane & 3) == 0) {
            sfm[rA * 2 + w2] = mxA;
            sfm[rB * 2 + w2] = mxB;
        }
        BARP(barid);
        mxA = fmaxf(sfm[rA * 2], sfm[rA * 2 + 1]);
        mxB = fmaxf(sfm[rB * 2], sfm[rB * 2 + 1]);

        float mnA = fmaxf(mA, mxA), mnB = fmaxf(mB, mxB);
        float alA = __expf(mA - mnA), alB = __expf(mB - mnB);
        float suA = 0.f, suB = 0.f;
#pragma unroll
        for (int nt = 0; nt < 4; nt++) {
            s[nt][0] = __expf(s[nt][0] - mnA);
            s[nt][1] = __expf(s[nt][1] - mnA);
            s[nt][2] = __expf(s[nt][2] - mnB);
            s[nt][3] = __expf(s[nt][3] - mnB);
            suA += s[nt][0] + s[nt][1];
            suB += s[nt][2] + s[nt][3];
        }
        suA += __shfl_xor_sync(0xffffffffu, suA, 1);
        suA += __shfl_xor_sync(0xffffffffu, suA, 2);
        suB += __shfl_xor_sync(0xffffffffu, suB, 1);
        suB += __shfl_xor_sync(0xffffffffu, suB, 2);
        if ((lane & 3) == 0) {
            sfs[rA * 2 + w2] = suA;
            sfs[rB * 2 + w2] = suB;
        }
        BARP(barid);
        lA = lA * alA + sfs[rA * 2] + sfs[rA * 2 + 1];
        lB = lB * alB + sfs[rB * 2] + sfs[rB * 2 + 1];
        mA = mnA;  mB = mnB;

        // ---- rescale O (overlaps V flight) ----
#pragma unroll
        for (int nt = 0; nt < 16; nt++) {
            O[nt][0] *= alA; O[nt][1] *= alA;
            O[nt][2] *= alB; O[nt][3] *= alB;
        }

        if (pre) { CP_WAIT(1); } else { CP_WAIT(0); }   // V(kb) complete
        __syncthreads();                                 // V visible

        // ---- O += P @ V on this warp's 32 keys ----
        const uint32_t vst = sb + AV_OFF + vfx;
#pragma unroll
        for (int kt = 0; kt < 2; kt++) {
            uint32_t ph[4], pl[4];
            split2(s[2 * kt][0],     s[2 * kt][1],     ph[0], pl[0]);
            split2(s[2 * kt][2],     s[2 * kt][3],     ph[1], pl[1]);
            split2(s[2 * kt + 1][0], s[2 * kt + 1][1], ph[2], pl[2]);
            split2(s[2 * kt + 1][2], s[2 * kt + 1][3], ph[3], pl[3]);
#pragma unroll
            for (int ntp = 0; ntp < 8; ntp++) {
                uint32_t va = vst + (uint32_t)(kt * 16 * AST + ntp * 32);
                uint32_t vh[4], vl[4];
                ldsm4t(vh, va);
                ldsm4t(vl, va + 17408);
                mma16816(O[2 * ntp],     ph, vh[0], vh[1]);
                mma16816(O[2 * ntp],     ph, vl[0], vl[1]);
                mma16816(O[2 * ntp],     pl, vh[0], vh[1]);
                mma16816(O[2 * ntp + 1], ph, vh[2], vh[3]);
                mma16816(O[2 * ntp + 1], ph, vl[2], vl[3]);
                mma16816(O[2 * ntp + 1], pl, vh[2], vh[3]);
            }
        }
    }

    // ---- epilogue: merge O halves across the pair, normalize, store ----
    // Reuses Q smem region (all Q reads ended before the last mid-iter sync).
    float* ex = (float*)sm + p * 2048;   // 8KB per pair
    if (w2 == 1) {
#pragma unroll
        for (int nt = 0; nt < 16; nt++)
#pragma unroll
            for (int e = 0; e < 4; e++)
                ex[lane * 64 + nt * 4 + e] = O[nt][e];
    }
    BARP(barid);
    if (w2 == 0) {
        const float liA = 1.f / lA, liB = 1.f / lB;
        const size_t rowA = (size_t)b * S_ + qb * 128 + rA;
#pragma unroll
        for (int nt = 0; nt < 16; nt++) {
            int cc = nt * 8 + (lane & 3) * 2;
            float o0 = O[nt][0] + ex[lane * 64 + nt * 4 + 0];
            float o1 = O[nt][1] + ex[lane * 64 + nt * 4 + 1];
            float o2 = O[nt][2] + ex[lane * 64 + nt * 4 + 2];
            float o3 = O[nt][3] + ex[lane * 64 + nt * 4 + 3];
            *(float2*)(out + rowA * H_ + cc) = make_float2(o0 * liA, o1 * liA);
            *(float2*)(out + (rowA + 8) * H_ + cc) = make_float2(o2 * liB, o3 * liB);
        }
    }
}

// ===========================================================================
// Launch
// ===========================================================================
extern "C" void kernel_launch(void* const* d_in, const int* in_sizes, int n_in,
                              void* d_out, int out_size)
{
    const float* input = (const float*)d_in[0];
    const float* Wq    = (const float*)d_in[1];
    const float* Wk    = (const float*)d_in[2];
    const float* Wv    = (const float*)d_in[3];
    float* out = (float*)d_out;

    cudaFuncSetAttribute(qkv_mma,
                         cudaFuncAttributeMaxDynamicSharedMemorySize, G_SMEM);
    cudaFuncSetAttribute(attn_mma,
                         cudaFuncAttributeMaxDynamicSharedMemorySize, A_SMEM);

    conv_a<<<(int)((size_t)M_ * D_ / 4 / 256), 256>>>(input);
    conv_w<<<dim3(512, 3), 256>>>(Wq, Wk, Wv);
    qkv_mma<<<dim3(M_ / 128, 3), 256, G_SMEM>>>();
    attn_mma<<<dim3(S_ / 128, B_), 512, A_SMEM>>>(out);
}